// round 9
// baseline (speedup 1.0000x reference)
#include <cuda_runtime.h>
#include <cstdint>
#include <math.h>

#define D    128
#define TQ   128
#define TK   64
#define KMAX 4096
#define NMAX 65536
#define NT64 (KMAX / 64)

// Fragment-packed operands in global (written by prep kernels, tf32-rounded):
// g_kf: [tile][ng(2)][s(16)][j(2)][lane(32)][4]  normalized keys (score side)
// g_vf: [tile][ng(2)][sv(4)][j(8)][lane(32)][4]  raw keys (value side)
// g_qf: [cta][slot(8)][s(16)][lane(32)][4]       normalized queries (slot = row>>4)
__device__ __align__(16) float g_kf[(size_t)NT64 * 8192];
__device__ __align__(16) float g_vf[(size_t)NT64 * 8192];
__device__ __align__(16) float g_qf[(size_t)(NMAX / TQ) * 16384];

// SMEM layout (bytes): QF | per-group double-buffered K/V chunks | DS
#define SM_QF  0            // 65536
#define SM_GRP 65536        // group ng: SM_GRP + ng*65536; buffer b at +b*32768 (K 16KB, V 16KB)
#define SM_DS  196608       // 1024
#define SMEM_TOTAL 197632

// ---------------- helpers ----------------
__device__ __forceinline__ uint32_t smem_u32(const void* p) {
    uint32_t a;
    asm("{ .reg .u64 t; cvta.to.shared.u64 t, %1; cvt.u32.u64 %0, t; }" : "=r"(a) : "l"(p));
    return a;
}
__device__ __forceinline__ void cp16(uint32_t s, const void* g) {
    asm volatile("cp.async.cg.shared.global [%0], [%1], 16;\n" :: "r"(s), "l"(g));
}
__device__ __forceinline__ void cp_commit() { asm volatile("cp.async.commit_group;\n" ::: "memory"); }
__device__ __forceinline__ void cp_wait0()  { asm volatile("cp.async.wait_group 0;\n" ::: "memory"); }
__device__ __forceinline__ void group_bar(int id) {
    asm volatile("bar.sync %0, %1;" :: "r"(id), "r"(256) : "memory");
}

__device__ __forceinline__ uint32_t to_tf32(float f) {
    uint32_t r;
    asm("cvt.rna.tf32.f32 %0, %1;" : "=r"(r) : "f"(f));
    return r;
}
__device__ __forceinline__ float to_tf32f(float f) { return __uint_as_float(to_tf32(f)); }

__device__ __forceinline__ void mma8(float* d,
                                     uint32_t a0, uint32_t a1, uint32_t a2, uint32_t a3,
                                     uint32_t b0, uint32_t b1) {
    asm volatile(
        "mma.sync.aligned.m16n8k8.row.col.f32.tf32.tf32.f32 "
        "{%0,%1,%2,%3},{%4,%5,%6,%7},{%8,%9},{%0,%1,%2,%3};\n"
        : "+f"(d[0]), "+f"(d[1]), "+f"(d[2]), "+f"(d[3])
        : "r"(a0), "r"(a1), "r"(a2), "r"(a3), "r"(b0), "r"(b1));
}
#define MMA8F(dst, A, b0, b1) \
    mma8(dst, __float_as_uint((A).x), __float_as_uint((A).y), \
              __float_as_uint((A).z), __float_as_uint((A).w), \
              __float_as_uint(b0), __float_as_uint(b1))

// Group tile chunk: 16KB K + 16KB V, loaded by the group's 256 threads (tg = tid&255)
__device__ __forceinline__ void load_group(uint32_t sb, int tg, int t, int ng) {
    const char* kg = reinterpret_cast<const char*>(g_kf) + (size_t)t * 32768 + ng * 16384;
    const char* vg = reinterpret_cast<const char*>(g_vf) + (size_t)t * 32768 + ng * 16384;
    const uint32_t kdst = SM_GRP + ng * 65536 + (t & 1) * 32768;
    const uint32_t vdst = kdst + 16384;
#pragma unroll
    for (int u = 0; u < 4; u++) {
        int id = u * 256 + tg;
        cp16(kdst + sb + id * 16, kg + id * 16);
    }
#pragma unroll
    for (int u = 0; u < 4; u++) {
        int id = u * 256 + tg;
        cp16(vdst + sb + id * 16, vg + id * 16);
    }
}

// ---------------------------------------------------------------------------
// Key prep: normalized (score) + raw (value) copies, tf32, fragment-packed.
// ---------------------------------------------------------------------------
__global__ void prep_kernel(const float* __restrict__ keys, int K) {
    int row = blockIdx.x * blockDim.y + threadIdx.y;
    if (row >= K) return;
    int lane = threadIdx.x;
    float4 v = reinterpret_cast<const float4*>(keys + (size_t)row * D)[lane];
    float ss = v.x * v.x + v.y * v.y + v.z * v.z + v.w * v.w;
#pragma unroll
    for (int o = 16; o; o >>= 1) ss += __shfl_xor_sync(0xffffffffu, ss, o);
    float s = 1.0f / fmaxf(sqrtf(ss), 1e-12f);

    int t = row >> 6, kt = row & 63;
    int ng = kt >> 5, r5 = kt & 31;
    int ntk = r5 >> 3, gk = r5 & 7;
    size_t kb = (size_t)t * 8192 + ng * 4096 + (ntk >> 1) * 128 + ((ntk & 1) << 1);
    int sv = r5 >> 3, tv = r5 & 3, hv = (r5 >> 2) & 1;
    size_t vb = (size_t)t * 8192 + ng * 4096 + sv * 1024 + hv;

    float vals[4] = {v.x, v.y, v.z, v.w};
#pragma unroll
    for (int c4 = 0; c4 < 4; c4++) {
        int c = 4 * lane + c4;
        int sK = c >> 3, tigK = c & 3, hK = (c >> 2) & 1;
        g_kf[kb + sK * 256 + (4 * gk + tigK) * 4 + hK] = to_tf32f(vals[c4] * s);
        int ntv = c >> 3, gv = c & 7;
        g_vf[vb + (ntv >> 1) * 128 + (4 * gv + tv) * 4 + ((ntv & 1) << 1)] = to_tf32f(vals[c4]);
    }
}

// ---------------------------------------------------------------------------
// Query prep: normalize, tf32, A-fragment-packed per CTA; slot = (row&127)>>4.
// ---------------------------------------------------------------------------
__global__ void prep_q(const float* __restrict__ queries, int N) {
    int row = blockIdx.x * blockDim.y + threadIdx.y;
    if (row >= N) return;
    int lane = threadIdx.x;
    float4 v = reinterpret_cast<const float4*>(queries + (size_t)row * D)[lane];
    float ss = v.x * v.x + v.y * v.y + v.z * v.z + v.w * v.w;
#pragma unroll
    for (int o = 16; o; o >>= 1) ss += __shfl_xor_sync(0xffffffffu, ss, o);
    float s = 1.0f / fmaxf(sqrtf(ss), 1e-12f);

    int cta = row >> 7, r = row & 127;
    int slot = r >> 4, h = (r >> 3) & 1, g = r & 7;
    size_t base = (size_t)cta * 16384 + slot * 2048 + g * 16 + h;

    float vals[4] = {v.x, v.y, v.z, v.w};
#pragma unroll
    for (int c4 = 0; c4 < 4; c4++) {
        int c = 4 * lane + c4;
        int sQ = c >> 3, tig = c & 3, chi = (c >> 2) & 1;
        g_qf[base + sQ * 128 + tig * 4 + 2 * chi] = to_tf32f(vals[c4] * s);
    }
}

// ---------------------------------------------------------------------------
// Fused flash kernel: 128 queries/CTA, 16 warps as two decoupled 8-warp
// pipelines; each warp owns a 16-row x 32-key tile, private O[16x128].
// ---------------------------------------------------------------------------
__global__ __launch_bounds__(512, 1)
void fused_mma(float* __restrict__ out, int K) {
    extern __shared__ __align__(16) float sm[];
    const uint32_t sb = smem_u32(sm);
    const int tid  = threadIdx.x;
    const int w    = tid >> 5;
    const int lane = tid & 31;
    const int g    = lane >> 2;
    const int tig  = lane & 3;
    const int ng   = w >> 3;         // group: warps 0-7 / 8-15
    const int mg   = w & 7;          // 16-row stripe within CTA tile
    const int tg   = tid & 255;      // group-local thread id
    const int q0   = blockIdx.x * TQ;
    const int niter = K / TK;

    // ---- prologue: QF (all threads) + group tile 0 ----
    {
        const char* qg = reinterpret_cast<const char*>(g_qf) + (size_t)blockIdx.x * 65536;
#pragma unroll
        for (int u = 0; u < 8; u++) {
            int id = u * 512 + tid;
            cp16(sb + SM_QF + id * 16, qg + id * 16);
        }
        load_group(sb, tg, 0, ng);
        cp_commit();
        cp_wait0();
    }
    __syncthreads();

    const float* qA = sm + mg * 2048 + lane * 4;

    float Oa[16][4];                 // rows 16mg+g (+8), d = 8j + 2tig (+1)
#pragma unroll
    for (int i = 0; i < 16; i++)
#pragma unroll
        for (int j = 0; j < 4; j++) Oa[i][j] = 0.f;
    float dacc[2] = {0.f, 0.f};

    const int src_a = (lane & 28) | (tig >> 1);
    const int src_b = src_a + 2;
    const bool odd  = (tig & 1);

    for (int it = 0; it < niter; it++) {
        if (it + 1 < niter) {          // prefetch next group chunk
            load_group(sb, tg, it + 1, ng);
            cp_commit();
        }

        const float* Ksb = sm + ((SM_GRP + ng * 65536 + (it & 1) * 32768) >> 2) + lane * 4;
        const float* Vsb = Ksb + 4096;

        // ---- GEMM1: S(16x32) = Qn . Kn^T ----
        float Sa[4][4];
#pragma unroll
        for (int i = 0; i < 4; i++)
#pragma unroll
            for (int j = 0; j < 4; j++) Sa[i][j] = 0.f;
#pragma unroll
        for (int s = 0; s < 16; s++) {
            float4 A0 = *reinterpret_cast<const float4*>(qA + s * 128);
            float4 B0 = *reinterpret_cast<const float4*>(Ksb + s * 256);
            float4 B1 = *reinterpret_cast<const float4*>(Ksb + s * 256 + 128);
            MMA8F(Sa[0], A0, B0.x, B0.y);
            MMA8F(Sa[1], A0, B0.z, B0.w);
            MMA8F(Sa[2], A0, B1.x, B1.y);
            MMA8F(Sa[3], A0, B1.z, B1.w);
        }

        // ---- softmax in registers (cosine scores => no max pass) ----
#pragma unroll
        for (int nt = 0; nt < 4; nt++) {
            float* f = Sa[nt];
#pragma unroll
            for (int e = 0; e < 4; e++) {
                float p = __expf(f[e]);
                dacc[e >> 1] += p;
                f[e] = to_tf32f(p);
            }
        }

        // ---- GEMM2: O(16x128 private) += P(regs) . V ----
#pragma unroll
        for (int s = 0; s < 4; s++) {
            const float* dreg = Sa[s];
            float x0 = __shfl_sync(0xffffffffu, dreg[0], src_a);
            float x1 = __shfl_sync(0xffffffffu, dreg[1], src_a);
            float x2 = __shfl_sync(0xffffffffu, dreg[2], src_a);
            float x3 = __shfl_sync(0xffffffffu, dreg[3], src_a);
            float y0 = __shfl_sync(0xffffffffu, dreg[0], src_b);
            float y1 = __shfl_sync(0xffffffffu, dreg[1], src_b);
            float y2 = __shfl_sync(0xffffffffu, dreg[2], src_b);
            float y3 = __shfl_sync(0xffffffffu, dreg[3], src_b);
            float4 A = make_float4(odd ? x1 : x0, odd ? x3 : x2,
                                   odd ? y1 : y0, odd ? y3 : y2);
            const float* vb = Vsb + s * 1024;
#pragma unroll
            for (int j = 0; j < 8; j++) {
                float4 Bf = *reinterpret_cast<const float4*>(vb + j * 128);
                MMA8F(Oa[2 * j],     A, Bf.x, Bf.y);
                MMA8F(Oa[2 * j + 1], A, Bf.z, Bf.w);
            }
        }

        if (it + 1 < niter) {
            cp_wait0();                // next tile landed
            group_bar(ng + 1);         // group-local visibility + buffer retire
        }
    }

    __syncthreads();   // join groups; QF/chunk regions free for epilogue

    float* DS = sm + SM_DS / 4;

    // ---- denominators ----
#pragma unroll
    for (int r = 0; r < 2; r++) {
        dacc[r] += __shfl_xor_sync(0xffffffffu, dacc[r], 1);
        dacc[r] += __shfl_xor_sync(0xffffffffu, dacc[r], 2);
    }
    if (tig == 0) {
#pragma unroll
        for (int r = 0; r < 2; r++) {
            int row = 16 * mg + g + 8 * r;
            DS[ng * 128 + row] = dacc[r];
        }
    }

    // ---- O pair-reduction: ng=0 publishes, ng=1 combines + writes ----
    float* Eb = sm + mg * 2176 + lane * 68;
    if (ng == 0) {
#pragma unroll
        for (int j = 0; j < 16; j++)
            *reinterpret_cast<float4*>(Eb + j * 4) =
                *reinterpret_cast<const float4*>(Oa[j]);
    }
    __syncthreads();

    if (ng == 1) {
        int row0 = 16 * mg + g;
        float i0 = 1.0f / (DS[row0] + DS[128 + row0]);
        float i1 = 1.0f / (DS[row0 + 8] + DS[128 + row0 + 8]);
        float* base0 = out + (size_t)(q0 + row0) * D + 2 * tig;
#pragma unroll
        for (int j = 0; j < 16; j++) {
            float4 p = *reinterpret_cast<const float4*>(Eb + j * 4);
            float2 o0 = make_float2((Oa[j][0] + p.x) * i0,
                                    (Oa[j][1] + p.y) * i0);
            float2 o1 = make_float2((Oa[j][2] + p.z) * i1,
                                    (Oa[j][3] + p.w) * i1);
            *reinterpret_cast<float2*>(base0 + 8 * j)         = o0;
            *reinterpret_cast<float2*>(base0 + 8 * j + 8 * D) = o1;
        }
    }
}

// ---------------------------------------------------------------------------
extern "C" void kernel_launch(void* const* d_in, const int* in_sizes, int n_in,
                              void* d_out, int out_size) {
    const float* queries = (const float*)d_in[0];
    const float* keys    = (const float*)d_in[1];
    float*       out     = (float*)d_out;

    int N = in_sizes[0] / D;
    int K = in_sizes[1] / D;

    cudaFuncSetAttribute(fused_mma, cudaFuncAttributeMaxDynamicSharedMemorySize, SMEM_TOTAL);

    prep_kernel<<<(K + 7) / 8, dim3(32, 8)>>>(keys, K);
    prep_q<<<(N + 7) / 8, dim3(32, 8)>>>(queries, N);
    fused_mma<<<N / TQ, 512, SMEM_TOTAL>>>(out, K);
}

// round 10
// speedup vs baseline: 1.0855x; 1.0855x over previous
#include <cuda_runtime.h>
#include <cstdint>
#include <math.h>

#define D    128
#define TQ   128
#define TK   64
#define KMAX 4096
#define NMAX 65536
#define NT64 (KMAX / 64)

// Fragment-packed operands in global (written by prep kernels, tf32-rounded):
// g_kf: [tile][ng(2)][s(16)][j(2)][lane(32)][4]  normalized keys (score side)
// g_vf: [tile][ng(2)][sv(4)][j(8)][lane(32)][4]  raw keys (value side)
// g_qf: [cta][slot(8)][s(16)][lane(32)][4]       normalized queries (slot = row>>4)
__device__ __align__(16) float g_kf[(size_t)NT64 * 8192];
__device__ __align__(16) float g_vf[(size_t)NT64 * 8192];
__device__ __align__(16) float g_qf[(size_t)(NMAX / TQ) * 16384];

// SMEM (bytes): QF fragments (reused as epilogue exchange) | DS
#define SM_QF  0            // 65536 (epilogue Eb overlays this after the loop)
#define SM_DS  67584        // 1024
#define SMEM_TOTAL 68608

// ---------------- helpers ----------------
__device__ __forceinline__ uint32_t smem_u32(const void* p) {
    uint32_t a;
    asm("{ .reg .u64 t; cvta.to.shared.u64 t, %1; cvt.u32.u64 %0, t; }" : "=r"(a) : "l"(p));
    return a;
}
__device__ __forceinline__ void cp16(uint32_t s, const void* g) {
    asm volatile("cp.async.cg.shared.global [%0], [%1], 16;\n" :: "r"(s), "l"(g));
}
__device__ __forceinline__ void cp_commit() { asm volatile("cp.async.commit_group;\n" ::: "memory"); }
__device__ __forceinline__ void cp_wait0()  { asm volatile("cp.async.wait_group 0;\n" ::: "memory"); }
__device__ __forceinline__ void group_bar(int id) {
    asm volatile("bar.sync %0, %1;" :: "r"(id), "r"(128) : "memory");
}

__device__ __forceinline__ uint32_t to_tf32(float f) {
    uint32_t r;
    asm("cvt.rna.tf32.f32 %0, %1;" : "=r"(r) : "f"(f));
    return r;
}
__device__ __forceinline__ float to_tf32f(float f) { return __uint_as_float(to_tf32(f)); }

__device__ __forceinline__ void mma8(float* d,
                                     uint32_t a0, uint32_t a1, uint32_t a2, uint32_t a3,
                                     uint32_t b0, uint32_t b1) {
    asm volatile(
        "mma.sync.aligned.m16n8k8.row.col.f32.tf32.tf32.f32 "
        "{%0,%1,%2,%3},{%4,%5,%6,%7},{%8,%9},{%0,%1,%2,%3};\n"
        : "+f"(d[0]), "+f"(d[1]), "+f"(d[2]), "+f"(d[3])
        : "r"(a0), "r"(a1), "r"(a2), "r"(a3), "r"(b0), "r"(b1));
}
#define MMA8F(dst, A, b0, b1) \
    mma8(dst, __float_as_uint((A).x), __float_as_uint((A).y), \
              __float_as_uint((A).z), __float_as_uint((A).w), \
              __float_as_uint(b0), __float_as_uint(b1))

// ---------------------------------------------------------------------------
// Key prep: normalized (score) + raw (value) copies, tf32, fragment-packed.
// ---------------------------------------------------------------------------
__global__ void prep_kernel(const float* __restrict__ keys, int K) {
    int row = blockIdx.x * blockDim.y + threadIdx.y;
    if (row >= K) return;
    int lane = threadIdx.x;
    float4 v = reinterpret_cast<const float4*>(keys + (size_t)row * D)[lane];
    float ss = v.x * v.x + v.y * v.y + v.z * v.z + v.w * v.w;
#pragma unroll
    for (int o = 16; o; o >>= 1) ss += __shfl_xor_sync(0xffffffffu, ss, o);
    float s = 1.0f / fmaxf(sqrtf(ss), 1e-12f);

    int t = row >> 6, kt = row & 63;
    int ng = kt >> 5, r5 = kt & 31;
    int ntk = r5 >> 3, gk = r5 & 7;
    size_t kb = (size_t)t * 8192 + ng * 4096 + (ntk >> 1) * 128 + ((ntk & 1) << 1);
    int sv = r5 >> 3, tv = r5 & 3, hv = (r5 >> 2) & 1;
    size_t vb = (size_t)t * 8192 + ng * 4096 + sv * 1024 + hv;

    float vals[4] = {v.x, v.y, v.z, v.w};
#pragma unroll
    for (int c4 = 0; c4 < 4; c4++) {
        int c = 4 * lane + c4;
        int sK = c >> 3, tigK = c & 3, hK = (c >> 2) & 1;
        g_kf[kb + sK * 256 + (4 * gk + tigK) * 4 + hK] = to_tf32f(vals[c4] * s);
        int ntv = c >> 3, gv = c & 7;
        g_vf[vb + (ntv >> 1) * 128 + (4 * gv + tv) * 4 + ((ntv & 1) << 1)] = to_tf32f(vals[c4]);
    }
}

// ---------------------------------------------------------------------------
// Query prep: normalize, tf32, A-fragment-packed per CTA; slot = (row&127)>>4.
// ---------------------------------------------------------------------------
__global__ void prep_q(const float* __restrict__ queries, int N) {
    int row = blockIdx.x * blockDim.y + threadIdx.y;
    if (row >= N) return;
    int lane = threadIdx.x;
    float4 v = reinterpret_cast<const float4*>(queries + (size_t)row * D)[lane];
    float ss = v.x * v.x + v.y * v.y + v.z * v.z + v.w * v.w;
#pragma unroll
    for (int o = 16; o; o >>= 1) ss += __shfl_xor_sync(0xffffffffu, ss, o);
    float s = 1.0f / fmaxf(sqrtf(ss), 1e-12f);

    int cta = row >> 7, r = row & 127;
    int slot = r >> 4, h = (r >> 3) & 1, g = r & 7;
    size_t base = (size_t)cta * 16384 + slot * 2048 + g * 16 + h;

    float vals[4] = {v.x, v.y, v.z, v.w};
#pragma unroll
    for (int c4 = 0; c4 < 4; c4++) {
        int c = 4 * lane + c4;
        int sQ = c >> 3, tig = c & 3, chi = (c >> 2) & 1;
        g_qf[base + sQ * 128 + tig * 4 + 2 * chi] = to_tf32f(vals[c4] * s);
    }
}

// ---------------------------------------------------------------------------
// Fused flash kernel: 128 queries/CTA, 8 warps (32x32 warp tiles).
// Q fragments from smem; K/V fragments streamed by direct coalesced LDG
// (L2-resident, L1-reused across the 4 warps of each ng-group).
// ---------------------------------------------------------------------------
__global__ __launch_bounds__(256, 1)
void fused_mma(float* __restrict__ out, int K) {
    extern __shared__ __align__(16) float sm[];
    const uint32_t sb = smem_u32(sm);
    const int tid  = threadIdx.x;
    const int w    = tid >> 5;
    const int lane = tid & 31;
    const int g    = lane >> 2;
    const int tig  = lane & 3;
    const int ng   = w >> 2;         // group: warps 0-3 / 4-7 (one per SMSP each)
    const int mg   = w & 3;          // 32-row stripe
    const int q0   = blockIdx.x * TQ;
    const int niter = K / TK;

    // ---- prologue: QF only ----
    {
        const char* qg = reinterpret_cast<const char*>(g_qf) + (size_t)blockIdx.x * 65536;
#pragma unroll
        for (int u = 0; u < 16; u++) {
            int id = u * 256 + tid;
            cp16(sb + SM_QF + id * 16, qg + id * 16);
        }
        cp_commit();
        cp_wait0();
    }
    __syncthreads();

    const float* qA = sm + (mg * 2) * 2048 + lane * 4;   // mt stride = 2048 floats

    float Oa[32][4];
#pragma unroll
    for (int i = 0; i < 32; i++)
#pragma unroll
        for (int j = 0; j < 4; j++) Oa[i][j] = 0.f;
    float dacc[4] = {0.f, 0.f, 0.f, 0.f};

    const int src_a = (lane & 28) | (tig >> 1);
    const int src_b = src_a + 2;
    const bool odd  = (tig & 1);

    const char* kgp = reinterpret_cast<const char*>(g_kf) + ng * 16384 + lane * 16;
    const char* vgp = reinterpret_cast<const char*>(g_vf) + ng * 16384 + lane * 16;

    for (int it = 0; it < niter; it++) {
        // ---- GEMM1: S(32x32) = Qn . Kn^T  (B via LDG.128 from L2/L1) ----
        float Sa[8][4];
#pragma unroll
        for (int i = 0; i < 8; i++)
#pragma unroll
            for (int j = 0; j < 4; j++) Sa[i][j] = 0.f;
#pragma unroll
        for (int s = 0; s < 16; s++) {
            float4 A0 = *reinterpret_cast<const float4*>(qA + s * 128);
            float4 A1 = *reinterpret_cast<const float4*>(qA + 2048 + s * 128);
            float4 B0 = *reinterpret_cast<const float4*>(kgp + s * 1024);
            float4 B1 = *reinterpret_cast<const float4*>(kgp + s * 1024 + 512);
            MMA8F(Sa[0], A0, B0.x, B0.y);
            MMA8F(Sa[4], A1, B0.x, B0.y);
            MMA8F(Sa[1], A0, B0.z, B0.w);
            MMA8F(Sa[5], A1, B0.z, B0.w);
            MMA8F(Sa[2], A0, B1.x, B1.y);
            MMA8F(Sa[6], A1, B1.x, B1.y);
            MMA8F(Sa[3], A0, B1.z, B1.w);
            MMA8F(Sa[7], A1, B1.z, B1.w);
        }

        // ---- softmax in registers (cosine scores => no max pass) ----
#pragma unroll
        for (int mt = 0; mt < 2; mt++)
#pragma unroll
            for (int nt = 0; nt < 4; nt++) {
                float* f = Sa[mt * 4 + nt];
#pragma unroll
                for (int e = 0; e < 4; e++) {
                    float p = __expf(f[e]);
                    dacc[mt * 2 + (e >> 1)] += p;
                    f[e] = to_tf32f(p);
                }
            }

        // ---- GEMM2: O(32x128 private) += P(regs) . V  (B via LDG.128) ----
#pragma unroll
        for (int s = 0; s < 4; s++) {
            float4 A[2];
#pragma unroll
            for (int mt = 0; mt < 2; mt++) {
                const float* dreg = Sa[mt * 4 + s];
                float x0 = __shfl_sync(0xffffffffu, dreg[0], src_a);
                float x1 = __shfl_sync(0xffffffffu, dreg[1], src_a);
                float x2 = __shfl_sync(0xffffffffu, dreg[2], src_a);
                float x3 = __shfl_sync(0xffffffffu, dreg[3], src_a);
                float y0 = __shfl_sync(0xffffffffu, dreg[0], src_b);
                float y1 = __shfl_sync(0xffffffffu, dreg[1], src_b);
                float y2 = __shfl_sync(0xffffffffu, dreg[2], src_b);
                float y3 = __shfl_sync(0xffffffffu, dreg[3], src_b);
                A[mt] = make_float4(odd ? x1 : x0, odd ? x3 : x2,
                                    odd ? y1 : y0, odd ? y3 : y2);
            }
            const char* vb = vgp + s * 4096;
#pragma unroll
            for (int j = 0; j < 8; j++) {
                float4 Bf = *reinterpret_cast<const float4*>(vb + j * 512);
                MMA8F(Oa[2 * j],          A[0], Bf.x, Bf.y);
                MMA8F(Oa[16 + 2 * j],     A[1], Bf.x, Bf.y);
                MMA8F(Oa[2 * j + 1],      A[0], Bf.z, Bf.w);
                MMA8F(Oa[16 + 2 * j + 1], A[1], Bf.z, Bf.w);
            }
        }

        kgp += 32768;
        vgp += 32768;
        group_bar(ng + 1);             // bound group slip -> keep L1 reuse hot
    }

    __syncthreads();   // join groups; QF region free for epilogue exchange

    float* DS = sm + SM_DS / 4;

    // ---- denominators ----
#pragma unroll
    for (int r = 0; r < 4; r++) {
        dacc[r] += __shfl_xor_sync(0xffffffffu, dacc[r], 1);
        dacc[r] += __shfl_xor_sync(0xffffffffu, dacc[r], 2);
    }
    if (tig == 0) {
#pragma unroll
        for (int r = 0; r < 4; r++) {
            int row = 32 * mg + 16 * (r >> 1) + g + ((r & 1) << 3);
            DS[ng * 128 + row] = dacc[r];
        }
    }

    // ---- O pair-reduction: ng=0 publishes, ng=1 combines + writes ----
    float* Eb = sm + mg * 4224 + lane * 132;
    if (ng == 0) {
#pragma unroll
        for (int j = 0; j < 32; j++)
            *reinterpret_cast<float4*>(Eb + j * 4) =
                *reinterpret_cast<const float4*>(Oa[j]);
    }
    __syncthreads();

    if (ng == 1) {
#pragma unroll
        for (int mt = 0; mt < 2; mt++) {
            int row0 = 32 * mg + 16 * mt + g;
            float i0 = 1.0f / (DS[row0] + DS[128 + row0]);
            float i1 = 1.0f / (DS[row0 + 8] + DS[128 + row0 + 8]);
#pragma unroll
            for (int nt = 0; nt < 16; nt++) {
                int j = mt * 16 + nt;
                float4 p = *reinterpret_cast<const float4*>(Eb + j * 4);
                float2 o0 = make_float2((Oa[j][0] + p.x) * i0,
                                        (Oa[j][1] + p.y) * i0);
                float2 o1 = make_float2((Oa[j][2] + p.z) * i1,
                                        (Oa[j][3] + p.w) * i1);
                float* base = out + (size_t)(q0 + row0) * D + 8 * nt + 2 * tig;
                *reinterpret_cast<float2*>(base)         = o0;
                *reinterpret_cast<float2*>(base + 8 * D) = o1;
            }
        }
    }
}

// ---------------------------------------------------------------------------
extern "C" void kernel_launch(void* const* d_in, const int* in_sizes, int n_in,
                              void* d_out, int out_size) {
    const float* queries = (const float*)d_in[0];
    const float* keys    = (const float*)d_in[1];
    float*       out     = (float*)d_out;

    int N = in_sizes[0] / D;
    int K = in_sizes[1] / D;

    cudaFuncSetAttribute(fused_mma, cudaFuncAttributeMaxDynamicSharedMemorySize, SMEM_TOTAL);

    prep_kernel<<<(K + 7) / 8, dim3(32, 8)>>>(keys, K);
    prep_q<<<(N + 7) / 8, dim3(32, 8)>>>(queries, N);
    fused_mma<<<N / TQ, 256, SMEM_TOTAL>>>(out, K);
}

// round 11
// speedup vs baseline: 1.5143x; 1.3951x over previous
#include <cuda_runtime.h>
#include <cuda_bf16.h>
#include <cstdint>
#include <math.h>

#define D    128
#define TQ   128
#define TK   64
#define KMAX 4096
#define NMAX 65536
#define NT64 (KMAX / 64)

// Fragment-packed operands in global (written by prep kernels):
// g_kfh: bf16x2 [tile][ng2][s8][j2][lane32][4]   normalized keys  (16KB/tile)
// g_vf : fp32   [tile][ng2][sv4][j8][lane32][4]  raw keys         (32KB/tile)
// g_qfh: bf16x2 [cta][slot8][s8][lane32][4]      normalized queries (32KB/cta)
__device__ __align__(16) uint32_t g_kfh[(size_t)NT64 * 4096];
__device__ __align__(16) float    g_vf [(size_t)NT64 * 8192];
__device__ __align__(16) uint32_t g_qfh[(size_t)(NMAX / TQ) * 8192];

// SMEM (bytes)
#define SM_QF  0            // 32768 : Q bf16 fragments (epilogue Eb overlays)
#define SM_GRP 32768        // group ng at +ng*49152; buf b at +b*24576 (K 8KB, V 16KB)
#define SM_DS  131072       // 1024
#define SMEM_TOTAL 132096

// ---------------- helpers ----------------
__device__ __forceinline__ uint32_t smem_u32(const void* p) {
    uint32_t a;
    asm("{ .reg .u64 t; cvta.to.shared.u64 t, %1; cvt.u32.u64 %0, t; }" : "=r"(a) : "l"(p));
    return a;
}
__device__ __forceinline__ void cp16(uint32_t s, const void* g) {
    asm volatile("cp.async.cg.shared.global [%0], [%1], 16;\n" :: "r"(s), "l"(g));
}
__device__ __forceinline__ void cp_commit() { asm volatile("cp.async.commit_group;\n" ::: "memory"); }
__device__ __forceinline__ void cp_wait0()  { asm volatile("cp.async.wait_group 0;\n" ::: "memory"); }
__device__ __forceinline__ void group_bar(int id) {
    asm volatile("bar.sync %0, %1;" :: "r"(id), "r"(128) : "memory");
}

__device__ __forceinline__ uint32_t to_tf32(float f) {
    uint32_t r;
    asm("cvt.rna.tf32.f32 %0, %1;" : "=r"(r) : "f"(f));
    return r;
}
__device__ __forceinline__ float to_tf32f(float f) { return __uint_as_float(to_tf32(f)); }
__device__ __forceinline__ uint32_t bf2(float lo, float hi) {
    __nv_bfloat162 t = __floats2bfloat162_rn(lo, hi);   // .x = lo half
    return *reinterpret_cast<uint32_t*>(&t);
}

// tf32 k8 (GEMM2)
__device__ __forceinline__ void mma8(float* d,
                                     uint32_t a0, uint32_t a1, uint32_t a2, uint32_t a3,
                                     uint32_t b0, uint32_t b1) {
    asm volatile(
        "mma.sync.aligned.m16n8k8.row.col.f32.tf32.tf32.f32 "
        "{%0,%1,%2,%3},{%4,%5,%6,%7},{%8,%9},{%0,%1,%2,%3};\n"
        : "+f"(d[0]), "+f"(d[1]), "+f"(d[2]), "+f"(d[3])
        : "r"(a0), "r"(a1), "r"(a2), "r"(a3), "r"(b0), "r"(b1));
}
// bf16 k16 (GEMM1)
__device__ __forceinline__ void mma16(float* d,
                                      uint32_t a0, uint32_t a1, uint32_t a2, uint32_t a3,
                                      uint32_t b0, uint32_t b1) {
    asm volatile(
        "mma.sync.aligned.m16n8k16.row.col.f32.bf16.bf16.f32 "
        "{%0,%1,%2,%3},{%4,%5,%6,%7},{%8,%9},{%0,%1,%2,%3};\n"
        : "+f"(d[0]), "+f"(d[1]), "+f"(d[2]), "+f"(d[3])
        : "r"(a0), "r"(a1), "r"(a2), "r"(a3), "r"(b0), "r"(b1));
}
#define MMA8F(dst, A, b0, b1) \
    mma8(dst, __float_as_uint((A).x), __float_as_uint((A).y), \
              __float_as_uint((A).z), __float_as_uint((A).w), \
              __float_as_uint(b0), __float_as_uint(b1))
#define MMA16F(dst, A, b0, b1) \
    mma16(dst, __float_as_uint((A).x), __float_as_uint((A).y), \
               __float_as_uint((A).z), __float_as_uint((A).w), \
               __float_as_uint(b0), __float_as_uint(b1))

// Group chunk: 8KB K(bf16) + 16KB V(fp32), by the group's 128 threads
__device__ __forceinline__ void load_group(uint32_t sb, int tg, int t, int ng) {
    const char* kg = reinterpret_cast<const char*>(g_kfh) + (size_t)t * 16384 + ng * 8192;
    const char* vg = reinterpret_cast<const char*>(g_vf)  + (size_t)t * 32768 + ng * 16384;
    const uint32_t kdst = SM_GRP + ng * 49152 + (t & 1) * 24576;
    const uint32_t vdst = kdst + 8192;
#pragma unroll
    for (int u = 0; u < 4; u++) {
        int id = u * 128 + tg;
        cp16(kdst + sb + id * 16, kg + id * 16);
    }
#pragma unroll
    for (int u = 0; u < 8; u++) {
        int id = u * 128 + tg;
        cp16(vdst + sb + id * 16, vg + id * 16);
    }
}

// ---------------------------------------------------------------------------
// Key prep: bf16 normalized (score, k16 fragment layout) + fp32 raw (value).
// ---------------------------------------------------------------------------
__global__ void prep_kernel(const float* __restrict__ keys, int K) {
    int row = blockIdx.x * blockDim.y + threadIdx.y;
    if (row >= K) return;
    int lane = threadIdx.x;
    float4 v = reinterpret_cast<const float4*>(keys + (size_t)row * D)[lane];
    float ss = v.x * v.x + v.y * v.y + v.z * v.z + v.w * v.w;
#pragma unroll
    for (int o = 16; o; o >>= 1) ss += __shfl_xor_sync(0xffffffffu, ss, o);
    float s = 1.0f / fmaxf(sqrtf(ss), 1e-12f);

    int t = row >> 6, kt = row & 63;
    int ng = kt >> 5, r5 = kt & 31;
    int nt = r5 >> 3, gk = r5 & 7;
    int j = nt >> 1, npar = nt & 1;
    size_t kbase = (size_t)t * 4096 + ng * 2048 + j * 128 + 2 * npar;

    int sv = r5 >> 3, tv = r5 & 3, hv = (r5 >> 2) & 1;
    size_t vb = (size_t)t * 8192 + ng * 4096 + sv * 1024 + hv;

    float vals[4] = {v.x, v.y, v.z, v.w};
    // bf16 score copy: u32 pairs (d, d+1) for d = 4*lane, 4*lane+2
#pragma unroll
    for (int pr = 0; pr < 2; pr++) {
        int d = 4 * lane + 2 * pr;
        int dk = d & 15;
        int sK = d >> 4, tigK = (dk >> 1) & 3, bK = (dk >> 3) & 1;
        g_kfh[kbase + sK * 256 + (4 * gk + tigK) * 4 + bK] =
            bf2(vals[2 * pr] * s, vals[2 * pr + 1] * s);
    }
    // fp32 value copy (tf32-rounded), k8 fragment layout
#pragma unroll
    for (int c4 = 0; c4 < 4; c4++) {
        int c = 4 * lane + c4;
        int ntv = c >> 3, gv = c & 7;
        g_vf[vb + (ntv >> 1) * 128 + (4 * gv + tv) * 4 + ((ntv & 1) << 1)] = to_tf32f(vals[c4]);
    }
}

// ---------------------------------------------------------------------------
// Query prep: bf16 normalized, k16 A-fragment layout; slot = (row&127)>>4.
// ---------------------------------------------------------------------------
__global__ void prep_q(const float* __restrict__ queries, int N) {
    int row = blockIdx.x * blockDim.y + threadIdx.y;
    if (row >= N) return;
    int lane = threadIdx.x;
    float4 v = reinterpret_cast<const float4*>(queries + (size_t)row * D)[lane];
    float ss = v.x * v.x + v.y * v.y + v.z * v.z + v.w * v.w;
#pragma unroll
    for (int o = 16; o; o >>= 1) ss += __shfl_xor_sync(0xffffffffu, ss, o);
    float s = 1.0f / fmaxf(sqrtf(ss), 1e-12f);

    int cta = row >> 7, r7 = row & 127;
    int slot = r7 >> 4, rr = r7 & 15;
    int p = rr >> 3, gq = rr & 7;
    size_t qbase = (size_t)cta * 8192 + slot * 1024 + p;

    float vals[4] = {v.x, v.y, v.z, v.w};
#pragma unroll
    for (int pr = 0; pr < 2; pr++) {
        int d = 4 * lane + 2 * pr;
        int dk = d & 15;
        int sQ = d >> 4, tigQ = (dk >> 1) & 3, bQ = (dk >> 3) & 1;
        g_qfh[qbase + sQ * 128 + (4 * gq + tigQ) * 4 + 2 * bQ] =
            bf2(vals[2 * pr] * s, vals[2 * pr + 1] * s);
    }
}

// ---------------------------------------------------------------------------
// Fused flash kernel: 128 queries/CTA, 8 warps, two decoupled 4-warp groups.
// GEMM1 bf16 m16n8k16; softmax fp32; GEMM2 tf32 m16n8k8.
// ---------------------------------------------------------------------------
__global__ __launch_bounds__(256, 1)
void fused_mma(float* __restrict__ out, int K) {
    extern __shared__ __align__(16) float sm[];
    const uint32_t sb = smem_u32(sm);
    const int tid  = threadIdx.x;
    const int w    = tid >> 5;
    const int lane = tid & 31;
    const int g    = lane >> 2;
    const int tig  = lane & 3;
    const int ng   = w >> 2;         // group: warps 0-3 / 4-7
    const int mg   = w & 3;          // 32-row stripe
    const int tg   = tid & 127;
    const int q0   = blockIdx.x * TQ;
    const int niter = K / TK;

    // ---- prologue: QF bf16 (2048 chunks) + group tile 0 ----
    {
        const char* qg = reinterpret_cast<const char*>(g_qfh) + (size_t)blockIdx.x * 32768;
#pragma unroll
        for (int u = 0; u < 8; u++) {
            int id = u * 256 + tid;
            cp16(sb + SM_QF + id * 16, qg + id * 16);
        }
        load_group(sb, tg, 0, ng);
        cp_commit();
        cp_wait0();
    }
    __syncthreads();

    const float4* qA4 = reinterpret_cast<const float4*>(sm) + (2 * mg) * 64 + lane;
    // slot stride = 8 s * 32 = 256 float4? NO: s stride = 32 f4, slot stride = 8*32 = 256 f4.
    // qA4 base uses slot0 = 2*mg: offset (2*mg)*256... fixed below via explicit indices.

    float Oa[32][4];
#pragma unroll
    for (int i = 0; i < 32; i++)
#pragma unroll
        for (int j = 0; j < 4; j++) Oa[i][j] = 0.f;
    float dacc[4] = {0.f, 0.f, 0.f, 0.f};

    const int src_a = (lane & 28) | (tig >> 1);
    const int src_b = src_a + 2;
    const bool odd  = (tig & 1);

    const float4* qAs = reinterpret_cast<const float4*>(sm) + (2 * mg) * 256 + lane;

    for (int it = 0; it < niter; it++) {
        if (it + 1 < niter) {          // prefetch next group chunk
            load_group(sb, tg, it + 1, ng);
            cp_commit();
        }

        const float4* kb4 = reinterpret_cast<const float4*>(sm)
                          + ((SM_GRP + ng * 49152 + (it & 1) * 24576) >> 4) + lane;
        const float4* vb4 = kb4 + 512;   // V region starts 8192B into the buffer

        // ---- GEMM1 (bf16 k16): S(32x32) = Qn . Kn^T ----
        float Sa[8][4];
#pragma unroll
        for (int i = 0; i < 8; i++)
#pragma unroll
            for (int j = 0; j < 4; j++) Sa[i][j] = 0.f;
#pragma unroll
        for (int s = 0; s < 8; s++) {
            float4 A0 = qAs[s * 32];
            float4 A1 = qAs[s * 32 + 256];
            float4 B0 = kb4[s * 64];
            float4 B1 = kb4[s * 64 + 32];
            MMA16F(Sa[0], A0, B0.x, B0.y);
            MMA16F(Sa[4], A1, B0.x, B0.y);
            MMA16F(Sa[1], A0, B0.z, B0.w);
            MMA16F(Sa[5], A1, B0.z, B0.w);
            MMA16F(Sa[2], A0, B1.x, B1.y);
            MMA16F(Sa[6], A1, B1.x, B1.y);
            MMA16F(Sa[3], A0, B1.z, B1.w);
            MMA16F(Sa[7], A1, B1.z, B1.w);
        }

        // ---- softmax in registers (cosine scores => no max pass) ----
#pragma unroll
        for (int mt = 0; mt < 2; mt++)
#pragma unroll
            for (int nt = 0; nt < 4; nt++) {
                float* f = Sa[mt * 4 + nt];
#pragma unroll
                for (int e = 0; e < 4; e++) {
                    float p = __expf(f[e]);
                    dacc[mt * 2 + (e >> 1)] += p;
                    f[e] = to_tf32f(p);
                }
            }

        // ---- GEMM2 (tf32 k8): O(32x128 private) += P(regs) . V ----
#pragma unroll
        for (int s = 0; s < 4; s++) {
            float4 A[2];
#pragma unroll
            for (int mt = 0; mt < 2; mt++) {
                const float* dreg = Sa[mt * 4 + s];
                float x0 = __shfl_sync(0xffffffffu, dreg[0], src_a);
                float x1 = __shfl_sync(0xffffffffu, dreg[1], src_a);
                float x2 = __shfl_sync(0xffffffffu, dreg[2], src_a);
                float x3 = __shfl_sync(0xffffffffu, dreg[3], src_a);
                float y0 = __shfl_sync(0xffffffffu, dreg[0], src_b);
                float y1 = __shfl_sync(0xffffffffu, dreg[1], src_b);
                float y2 = __shfl_sync(0xffffffffu, dreg[2], src_b);
                float y3 = __shfl_sync(0xffffffffu, dreg[3], src_b);
                A[mt] = make_float4(odd ? x1 : x0, odd ? x3 : x2,
                                    odd ? y1 : y0, odd ? y3 : y2);
            }
#pragma unroll
            for (int j = 0; j < 8; j++) {
                float4 Bf = vb4[(s * 8 + j) * 32];
                MMA8F(Oa[2 * j],          A[0], Bf.x, Bf.y);
                MMA8F(Oa[16 + 2 * j],     A[1], Bf.x, Bf.y);
                MMA8F(Oa[2 * j + 1],      A[0], Bf.z, Bf.w);
                MMA8F(Oa[16 + 2 * j + 1], A[1], Bf.z, Bf.w);
            }
        }

        if (it + 1 < niter) {
            cp_wait0();                // next tile landed
            group_bar(ng + 1);         // group-local visibility + buffer retire
        }
    }

    __syncthreads();   // join groups; QF + group regions free for epilogue

    float* DS = sm + SM_DS / 4;

    // ---- denominators ----
#pragma unroll
    for (int r = 0; r < 4; r++) {
        dacc[r] += __shfl_xor_sync(0xffffffffu, dacc[r], 1);
        dacc[r] += __shfl_xor_sync(0xffffffffu, dacc[r], 2);
    }
    if (tig == 0) {
#pragma unroll
        for (int r = 0; r < 4; r++) {
            int row = 32 * mg + 16 * (r >> 1) + g + ((r & 1) << 3);
            DS[ng * 128 + row] = dacc[r];
        }
    }

    // ---- O pair-reduction: ng=0 publishes, ng=1 combines + writes ----
    float* Eb = sm + mg * 4224 + lane * 132;
    if (ng == 0) {
#pragma unroll
        for (int j = 0; j < 32; j++)
            *reinterpret_cast<float4*>(Eb + j * 4) =
                *reinterpret_cast<const float4*>(Oa[j]);
    }
    __syncthreads();

    if (ng == 1) {
#pragma unroll
        for (int mt = 0; mt < 2; mt++) {
            int row0 = 32 * mg + 16 * mt + g;
            float i0 = 1.0f / (DS[row0] + DS[128 + row0]);
            float i1 = 1.0f / (DS[row0 + 8] + DS[128 + row0 + 8]);
#pragma unroll
            for (int nt = 0; nt < 16; nt++) {
                int j = mt * 16 + nt;
                float4 p = *reinterpret_cast<const float4*>(Eb + j * 4);
                float2 o0 = make_float2((Oa[j][0] + p.x) * i0,
                                        (Oa[j][1] + p.y) * i0);
                float2 o1 = make_float2((Oa[j][2] + p.z) * i1,
                                        (Oa[j][3] + p.w) * i1);
                float* base = out + (size_t)(q0 + row0) * D + 8 * nt + 2 * tig;
                *reinterpret_cast<float2*>(base)         = o0;
                *reinterpret_cast<float2*>(base + 8 * D) = o1;
            }
        }
    }
}

// ---------------------------------------------------------------------------
extern "C" void kernel_launch(void* const* d_in, const int* in_sizes, int n_in,
                              void* d_out, int out_size) {
    const float* queries = (const float*)d_in[0];
    const float* keys    = (const float*)d_in[1];
    float*       out     = (float*)d_out;

    int N = in_sizes[0] / D;
    int K = in_sizes[1] / D;

    cudaFuncSetAttribute(fused_mma, cudaFuncAttributeMaxDynamicSharedMemorySize, SMEM_TOTAL);

    prep_kernel<<<(K + 7) / 8, dim3(32, 8)>>>(keys, K);
    prep_q<<<(N + 7) / 8, dim3(32, 8)>>>(queries, N);
    fused_mma<<<N / TQ, 256, SMEM_TOTAL>>>(out, K);
}

// round 12
// speedup vs baseline: 2.3014x; 1.5197x over previous
#include <cuda_runtime.h>
#include <cuda_bf16.h>
#include <cuda_fp16.h>
#include <cstdint>
#include <math.h>

#define D    128
#define TQ   128
#define TK   64
#define KMAX 4096
#define NMAX 65536
#define NT64 (KMAX / 64)

// Fragment-packed operands in global (written by prep kernels):
// g_kfh: bf16x2 [tile][ng2][s8][j2][lane32][4]      normalized keys (16KB/tile)
// g_vfh: fp16x2 [tile][ng2][kk2][jp8][lane32][4]    raw keys        (16KB/tile)
// g_qfh: bf16x2 [cta][slot8][s8][lane32][4]         normalized queries (32KB/cta)
__device__ __align__(16) uint32_t g_kfh[(size_t)NT64 * 4096];
__device__ __align__(16) uint32_t g_vfh[(size_t)NT64 * 4096];
__device__ __align__(16) uint32_t g_qfh[(size_t)(NMAX / TQ) * 8192];

// SMEM (bytes)
#define SM_QF  0            // 32768 : Q bf16 fragments (epilogue Eb overlays)
#define SM_GRP 32768        // group ng at +ng*32768; buf b at +b*16384 (K 8KB, V 8KB)
#define SM_DS  98304        // 1024
#define SMEM_TOTAL 99328

// ---------------- helpers ----------------
__device__ __forceinline__ uint32_t smem_u32(const void* p) {
    uint32_t a;
    asm("{ .reg .u64 t; cvta.to.shared.u64 t, %1; cvt.u32.u64 %0, t; }" : "=r"(a) : "l"(p));
    return a;
}
__device__ __forceinline__ void cp16(uint32_t s, const void* g) {
    asm volatile("cp.async.cg.shared.global [%0], [%1], 16;\n" :: "r"(s), "l"(g));
}
__device__ __forceinline__ void cp_commit() { asm volatile("cp.async.commit_group;\n" ::: "memory"); }
__device__ __forceinline__ void cp_wait0()  { asm volatile("cp.async.wait_group 0;\n" ::: "memory"); }
__device__ __forceinline__ void group_bar(int id) {
    asm volatile("bar.sync %0, %1;" :: "r"(id), "r"(128) : "memory");
}
__device__ __forceinline__ uint32_t bf2(float lo, float hi) {
    __nv_bfloat162 t = __floats2bfloat162_rn(lo, hi);   // .x = lo half
    return *reinterpret_cast<uint32_t*>(&t);
}
// pack two fp32 -> fp16x2 {lo, hi}
__device__ __forceinline__ uint32_t h2(float lo, float hi) {
    uint32_t r;
    asm("cvt.rn.f16x2.f32 %0, %1, %2;" : "=r"(r) : "f"(hi), "f"(lo));
    return r;
}

// bf16 k16 (GEMM1)
__device__ __forceinline__ void mma16b(float* d,
                                       uint32_t a0, uint32_t a1, uint32_t a2, uint32_t a3,
                                       uint32_t b0, uint32_t b1) {
    asm volatile(
        "mma.sync.aligned.m16n8k16.row.col.f32.bf16.bf16.f32 "
        "{%0,%1,%2,%3},{%4,%5,%6,%7},{%8,%9},{%0,%1,%2,%3};\n"
        : "+f"(d[0]), "+f"(d[1]), "+f"(d[2]), "+f"(d[3])
        : "r"(a0), "r"(a1), "r"(a2), "r"(a3), "r"(b0), "r"(b1));
}
// fp16 k16 (GEMM2)
__device__ __forceinline__ void mma16h(float* d,
                                       uint32_t a0, uint32_t a1, uint32_t a2, uint32_t a3,
                                       uint32_t b0, uint32_t b1) {
    asm volatile(
        "mma.sync.aligned.m16n8k16.row.col.f32.f16.f16.f32 "
        "{%0,%1,%2,%3},{%4,%5,%6,%7},{%8,%9},{%0,%1,%2,%3};\n"
        : "+f"(d[0]), "+f"(d[1]), "+f"(d[2]), "+f"(d[3])
        : "r"(a0), "r"(a1), "r"(a2), "r"(a3), "r"(b0), "r"(b1));
}
#define MMA16BF(dst, A, b0, b1) \
    mma16b(dst, __float_as_uint((A).x), __float_as_uint((A).y), \
                __float_as_uint((A).z), __float_as_uint((A).w), \
                __float_as_uint(b0), __float_as_uint(b1))

// Group chunk: 8KB K(bf16) + 8KB V(fp16), by the group's 128 threads
__device__ __forceinline__ void load_group(uint32_t sb, int tg, int t, int ng) {
    const char* kg = reinterpret_cast<const char*>(g_kfh) + (size_t)t * 16384 + ng * 8192;
    const char* vg = reinterpret_cast<const char*>(g_vfh) + (size_t)t * 16384 + ng * 8192;
    const uint32_t kdst = SM_GRP + ng * 32768 + (t & 1) * 16384;
    const uint32_t vdst = kdst + 8192;
#pragma unroll
    for (int u = 0; u < 4; u++) {
        int id = u * 128 + tg;
        cp16(kdst + sb + id * 16, kg + id * 16);
    }
#pragma unroll
    for (int u = 0; u < 4; u++) {
        int id = u * 128 + tg;
        cp16(vdst + sb + id * 16, vg + id * 16);
    }
}

// ---------------------------------------------------------------------------
// Key prep: bf16 normalized (score, k16 B layout) + fp16 raw (value, k16 B).
// ---------------------------------------------------------------------------
__global__ void prep_kernel(const float* __restrict__ keys, int K) {
    int row = blockIdx.x * blockDim.y + threadIdx.y;
    if (row >= K) return;
    int lane = threadIdx.x;
    float4 v = reinterpret_cast<const float4*>(keys + (size_t)row * D)[lane];
    float ss = v.x * v.x + v.y * v.y + v.z * v.z + v.w * v.w;
#pragma unroll
    for (int o = 16; o; o >>= 1) ss += __shfl_xor_sync(0xffffffffu, ss, o);
    float s = 1.0f / fmaxf(sqrtf(ss), 1e-12f);

    int t = row >> 6, kt = row & 63;
    int ng = kt >> 5, r5 = kt & 31;

    // score copy (bf16): nt/gk decomposition, layout [s8][j2][lane32][4]
    {
        int nt = r5 >> 3, gk = r5 & 7;
        int j = nt >> 1, npar = nt & 1;
        size_t kbase = (size_t)t * 4096 + ng * 2048 + j * 128 + 2 * npar;
        float vals[4] = {v.x, v.y, v.z, v.w};
#pragma unroll
        for (int pr = 0; pr < 2; pr++) {
            int d = 4 * lane + 2 * pr;
            int dk = d & 15;
            int sK = d >> 4, tigK = (dk >> 1) & 3, bK = (dk >> 3) & 1;
            g_kfh[kbase + sK * 256 + (4 * gk + tigK) * 4 + bK] =
                bf2(vals[2 * pr] * s, vals[2 * pr + 1] * s);
        }
    }

    // value copy (fp16): k16 B layout [kk2][jp8][lane32][4], u32 = {krel, krel+1}
    {
        int kk = r5 >> 4, krel = r5 & 15;
        int hb = krel >> 3, rr = krel & 7;
        int tigV = rr >> 1, lo = rr & 1;
        size_t vbase = (size_t)t * 4096 + ng * 2048 + kk * 1024;
        __half* vh = reinterpret_cast<__half*>(g_vfh);
        float vals[4] = {v.x, v.y, v.z, v.w};
#pragma unroll
        for (int c4 = 0; c4 < 4; c4++) {
            int d = 4 * lane + c4;
            int gV = d & 7, j = d >> 3, jp = j >> 1, jo = j & 1;
            size_t u = vbase + jp * 128 + (4 * gV + tigV) * 4 + jo * 2 + hb;
            vh[u * 2 + lo] = __float2half_rn(vals[c4]);
        }
    }
}

// ---------------------------------------------------------------------------
// Query prep: bf16 normalized, k16 A-fragment layout; slot = (row&127)>>4.
// ---------------------------------------------------------------------------
__global__ void prep_q(const float* __restrict__ queries, int N) {
    int row = blockIdx.x * blockDim.y + threadIdx.y;
    if (row >= N) return;
    int lane = threadIdx.x;
    float4 v = reinterpret_cast<const float4*>(queries + (size_t)row * D)[lane];
    float ss = v.x * v.x + v.y * v.y + v.z * v.z + v.w * v.w;
#pragma unroll
    for (int o = 16; o; o >>= 1) ss += __shfl_xor_sync(0xffffffffu, ss, o);
    float s = 1.0f / fmaxf(sqrtf(ss), 1e-12f);

    int cta = row >> 7, r7 = row & 127;
    int slot = r7 >> 4, rr = r7 & 15;
    int p = rr >> 3, gq = rr & 7;
    size_t qbase = (size_t)cta * 8192 + slot * 1024 + p;

    float vals[4] = {v.x, v.y, v.z, v.w};
#pragma unroll
    for (int pr = 0; pr < 2; pr++) {
        int d = 4 * lane + 2 * pr;
        int dk = d & 15;
        int sQ = d >> 4, tigQ = (dk >> 1) & 3, bQ = (dk >> 3) & 1;
        g_qfh[qbase + sQ * 128 + (4 * gq + tigQ) * 4 + 2 * bQ] =
            bf2(vals[2 * pr] * s, vals[2 * pr + 1] * s);
    }
}

// ---------------------------------------------------------------------------
// Fused flash kernel: 128 queries/CTA, 8 warps, two decoupled 4-warp groups.
// GEMM1 bf16 k16; softmax fp32 -> fp16 pack (no shuffles); GEMM2 fp16 k16.
// ---------------------------------------------------------------------------
__global__ __launch_bounds__(256, 1)
void fused_mma(float* __restrict__ out, int K) {
    extern __shared__ __align__(16) float sm[];
    const uint32_t sb = smem_u32(sm);
    const int tid  = threadIdx.x;
    const int w    = tid >> 5;
    const int lane = tid & 31;
    const int g    = lane >> 2;
    const int tig  = lane & 3;
    const int ng   = w >> 2;         // group: warps 0-3 / 4-7
    const int mg   = w & 3;          // 32-row stripe
    const int tg   = tid & 127;
    const int q0   = blockIdx.x * TQ;
    const int niter = K / TK;

    // ---- prologue: QF bf16 + group tile 0 ----
    {
        const char* qg = reinterpret_cast<const char*>(g_qfh) + (size_t)blockIdx.x * 32768;
#pragma unroll
        for (int u = 0; u < 8; u++) {
            int id = u * 256 + tid;
            cp16(sb + SM_QF + id * 16, qg + id * 16);
        }
        load_group(sb, tg, 0, ng);
        cp_commit();
        cp_wait0();
    }
    __syncthreads();

    float Oa[32][4];
#pragma unroll
    for (int i = 0; i < 32; i++)
#pragma unroll
        for (int j = 0; j < 4; j++) Oa[i][j] = 0.f;
    float dacc[4] = {0.f, 0.f, 0.f, 0.f};

    const float4* qAs = reinterpret_cast<const float4*>(sm) + (2 * mg) * 256 + lane;

    for (int it = 0; it < niter; it++) {
        if (it + 1 < niter) {          // prefetch next group chunk
            load_group(sb, tg, it + 1, ng);
            cp_commit();
        }

        const float4* kb4 = reinterpret_cast<const float4*>(sm)
                          + ((SM_GRP + ng * 32768 + (it & 1) * 16384) >> 4) + lane;
        const float4* vb4 = kb4 + 512;   // V region 8192B into the buffer

        // ---- GEMM1 (bf16 k16): S(32x32) = Qn . Kn^T ----
        float Sa[8][4];
#pragma unroll
        for (int i = 0; i < 8; i++)
#pragma unroll
            for (int j = 0; j < 4; j++) Sa[i][j] = 0.f;
#pragma unroll
        for (int s = 0; s < 8; s++) {
            float4 A0 = qAs[s * 32];
            float4 A1 = qAs[s * 32 + 256];
            float4 B0 = kb4[s * 64];
            float4 B1 = kb4[s * 64 + 32];
            MMA16BF(Sa[0], A0, B0.x, B0.y);
            MMA16BF(Sa[4], A1, B0.x, B0.y);
            MMA16BF(Sa[1], A0, B0.z, B0.w);
            MMA16BF(Sa[5], A1, B0.z, B0.w);
            MMA16BF(Sa[2], A0, B1.x, B1.y);
            MMA16BF(Sa[6], A1, B1.x, B1.y);
            MMA16BF(Sa[3], A0, B1.z, B1.w);
            MMA16BF(Sa[7], A1, B1.z, B1.w);
        }

        // ---- softmax (cosine scores => no max pass); pack P to fp16x2 ----
        uint32_t Ph[8][2];
#pragma unroll
        for (int mt = 0; mt < 2; mt++)
#pragma unroll
            for (int nt = 0; nt < 4; nt++) {
                const float* f = Sa[mt * 4 + nt];
                float p0 = __expf(f[0]);
                float p1 = __expf(f[1]);
                float p2 = __expf(f[2]);
                float p3 = __expf(f[3]);
                dacc[mt * 2]     += p0 + p1;
                dacc[mt * 2 + 1] += p2 + p3;
                Ph[mt * 4 + nt][0] = h2(p0, p1);   // row g
                Ph[mt * 4 + nt][1] = h2(p2, p3);   // row g+8
            }

        // ---- GEMM2 (fp16 k16): O(32x128 private) += P . V ----
        // A fragments come straight from accumulator layout: no shuffles.
#pragma unroll
        for (int kk = 0; kk < 2; kk++) {
            uint32_t A0[2], A1[2], A2[2], A3[2];
#pragma unroll
            for (int mt = 0; mt < 2; mt++) {
                A0[mt] = Ph[mt * 4 + 2 * kk][0];
                A1[mt] = Ph[mt * 4 + 2 * kk][1];
                A2[mt] = Ph[mt * 4 + 2 * kk + 1][0];
                A3[mt] = Ph[mt * 4 + 2 * kk + 1][1];
            }
            const float4* vk = vb4 + kk * 256;
#pragma unroll
            for (int jp = 0; jp < 8; jp++) {
                float4 Bf = vk[jp * 32];
                uint32_t b0 = __float_as_uint(Bf.x), b1 = __float_as_uint(Bf.y);
                uint32_t b2 = __float_as_uint(Bf.z), b3 = __float_as_uint(Bf.w);
                mma16h(Oa[2 * jp],      A0[0], A1[0], A2[0], A3[0], b0, b1);
                mma16h(Oa[16 + 2 * jp], A0[1], A1[1], A2[1], A3[1], b0, b1);
                mma16h(Oa[2 * jp + 1],      A0[0], A1[0], A2[0], A3[0], b2, b3);
                mma16h(Oa[16 + 2 * jp + 1], A0[1], A1[1], A2[1], A3[1], b2, b3);
            }
        }

        if (it + 1 < niter) {
            cp_wait0();                // next tile landed
            group_bar(ng + 1);         // group-local visibility + buffer retire
        }
    }

    __syncthreads();   // join groups; QF + group regions free for epilogue

    float* DS = sm + SM_DS / 4;

    // ---- denominators ----
#pragma unroll
    for (int r = 0; r < 4; r++) {
        dacc[r] += __shfl_xor_sync(0xffffffffu, dacc[r], 1);
        dacc[r] += __shfl_xor_sync(0xffffffffu, dacc[r], 2);
    }
    if (tig == 0) {
#pragma unroll
        for (int r = 0; r < 4; r++) {
            int row = 32 * mg + 16 * (r >> 1) + g + ((r & 1) << 3);
            DS[ng * 128 + row] = dacc[r];
        }
    }

    // ---- O pair-reduction: ng=0 publishes, ng=1 combines + writes ----
    float* Eb = sm + mg * 4224 + lane * 132;
    if (ng == 0) {
#pragma unroll
        for (int j = 0; j < 32; j++)
            *reinterpret_cast<float4*>(Eb + j * 4) =
                *reinterpret_cast<const float4*>(Oa[j]);
    }
    __syncthreads();

    if (ng == 1) {
#pragma unroll
        for (int mt = 0; mt < 2; mt++) {
            int row0 = 32 * mg + 16 * mt + g;
            float i0 = 1.0f / (DS[row0] + DS[128 + row0]);
            float i1 = 1.0f / (DS[row0 + 8] + DS[128 + row0 + 8]);
#pragma unroll
            for (int nt = 0; nt < 16; nt++) {
                int j = mt * 16 + nt;
                float4 p = *reinterpret_cast<const float4*>(Eb + j * 4);
                float2 o0 = make_float2((Oa[j][0] + p.x) * i0,
                                        (Oa[j][1] + p.y) * i0);
                float2 o1 = make_float2((Oa[j][2] + p.z) * i1,
                                        (Oa[j][3] + p.w) * i1);
                float* base = out + (size_t)(q0 + row0) * D + 8 * nt + 2 * tig;
                *reinterpret_cast<float2*>(base)         = o0;
                *reinterpret_cast<float2*>(base + 8 * D) = o1;
            }
        }
    }
}

// ---------------------------------------------------------------------------
extern "C" void kernel_launch(void* const* d_in, const int* in_sizes, int n_in,
                              void* d_out, int out_size) {
    const float* queries = (const float*)d_in[0];
    const float* keys    = (const float*)d_in[1];
    float*       out     = (float*)d_out;

    int N = in_sizes[0] / D;
    int K = in_sizes[1] / D;

    cudaFuncSetAttribute(fused_mma, cudaFuncAttributeMaxDynamicSharedMemorySize, SMEM_TOTAL);

    prep_kernel<<<(K + 7) / 8, dim3(32, 8)>>>(keys, K);
    prep_q<<<(N + 7) / 8, dim3(32, 8)>>>(queries, N);
    fused_mma<<<N / TQ, 256, SMEM_TOTAL>>>(out, K);
}

// round 13
// speedup vs baseline: 2.6435x; 1.1487x over previous
#include <cuda_runtime.h>
#include <cuda_bf16.h>
#include <cuda_fp16.h>
#include <cstdint>
#include <math.h>

#define D     128
#define TQ    64
#define TK    64
#define KMAX  4096
#define NMAX  65536
#define NT64  (KMAX / 64)
#define LOG2E 1.4426950408889634f

// Fragment-packed operands in global (written by prep kernels):
// g_kfh: bf16x2 [tile][ng2][s8][j2][lane32][4]      normalized keys (16KB/tile)
// g_vfh: fp16x2 [tile][ng2][kk2][jp8][lane32][4]    raw keys        (16KB/tile)
// g_qfh: bf16x2 [cta64][slot4][s8][lane32][4]       normalized queries * log2e
__device__ __align__(16) uint32_t g_kfh[(size_t)NT64 * 4096];
__device__ __align__(16) uint32_t g_vfh[(size_t)NT64 * 4096];
__device__ __align__(16) uint32_t g_qfh[(size_t)(NMAX / TQ) * 4096];

// SMEM (bytes)
#define SM_QF  0            // 16384 : Q bf16 fragments (epilogue Eb overlays)
#define SM_GRP 16384        // group ng at +ng*32768; buf b at +b*16384 (K 8KB, V 8KB)
#define SM_DS  81920        // 512
#define SMEM_TOTAL 82432

// ---------------- helpers ----------------
__device__ __forceinline__ uint32_t smem_u32(const void* p) {
    uint32_t a;
    asm("{ .reg .u64 t; cvta.to.shared.u64 t, %1; cvt.u32.u64 %0, t; }" : "=r"(a) : "l"(p));
    return a;
}
__device__ __forceinline__ void cp16(uint32_t s, const void* g) {
    asm volatile("cp.async.cg.shared.global [%0], [%1], 16;\n" :: "r"(s), "l"(g));
}
__device__ __forceinline__ void cp_commit() { asm volatile("cp.async.commit_group;\n" ::: "memory"); }
__device__ __forceinline__ void cp_wait0()  { asm volatile("cp.async.wait_group 0;\n" ::: "memory"); }
__device__ __forceinline__ void group_bar(int id) {
    asm volatile("bar.sync %0, %1;" :: "r"(id), "r"(64) : "memory");
}
__device__ __forceinline__ uint32_t bf2(float lo, float hi) {
    __nv_bfloat162 t = __floats2bfloat162_rn(lo, hi);   // .x = lo half
    return *reinterpret_cast<uint32_t*>(&t);
}
__device__ __forceinline__ uint32_t h2(float lo, float hi) {
    uint32_t r;
    asm("cvt.rn.f16x2.f32 %0, %1, %2;" : "=r"(r) : "f"(hi), "f"(lo));
    return r;
}
__device__ __forceinline__ float ex2(float x) {
    float r;
    asm("ex2.approx.f32 %0, %1;" : "=f"(r) : "f"(x));
    return r;
}

// bf16 k16 (GEMM1)
__device__ __forceinline__ void mma16b(float* d,
                                       uint32_t a0, uint32_t a1, uint32_t a2, uint32_t a3,
                                       uint32_t b0, uint32_t b1) {
    asm volatile(
        "mma.sync.aligned.m16n8k16.row.col.f32.bf16.bf16.f32 "
        "{%0,%1,%2,%3},{%4,%5,%6,%7},{%8,%9},{%0,%1,%2,%3};\n"
        : "+f"(d[0]), "+f"(d[1]), "+f"(d[2]), "+f"(d[3])
        : "r"(a0), "r"(a1), "r"(a2), "r"(a3), "r"(b0), "r"(b1));
}
// fp16 k16 (GEMM2)
__device__ __forceinline__ void mma16h(float* d,
                                       uint32_t a0, uint32_t a1, uint32_t a2, uint32_t a3,
                                       uint32_t b0, uint32_t b1) {
    asm volatile(
        "mma.sync.aligned.m16n8k16.row.col.f32.f16.f16.f32 "
        "{%0,%1,%2,%3},{%4,%5,%6,%7},{%8,%9},{%0,%1,%2,%3};\n"
        : "+f"(d[0]), "+f"(d[1]), "+f"(d[2]), "+f"(d[3])
        : "r"(a0), "r"(a1), "r"(a2), "r"(a3), "r"(b0), "r"(b1));
}
#define MMA16BF(dst, A, b0, b1) \
    mma16b(dst, __float_as_uint((A).x), __float_as_uint((A).y), \
                __float_as_uint((A).z), __float_as_uint((A).w), \
                __float_as_uint(b0), __float_as_uint(b1))

// Group chunk: 8KB K(bf16) + 8KB V(fp16), by the group's 64 threads (tg)
__device__ __forceinline__ void load_group(uint32_t sb, int tg, int t, int ng) {
    const char* kg = reinterpret_cast<const char*>(g_kfh) + (size_t)t * 16384 + ng * 8192;
    const char* vg = reinterpret_cast<const char*>(g_vfh) + (size_t)t * 16384 + ng * 8192;
    const uint32_t kdst = SM_GRP + ng * 32768 + (t & 1) * 16384;
    const uint32_t vdst = kdst + 8192;
#pragma unroll
    for (int u = 0; u < 8; u++) {
        int id = u * 64 + tg;
        cp16(kdst + sb + id * 16, kg + id * 16);
    }
#pragma unroll
    for (int u = 0; u < 8; u++) {
        int id = u * 64 + tg;
        cp16(vdst + sb + id * 16, vg + id * 16);
    }
}

// ---------------------------------------------------------------------------
// Key prep: bf16 normalized (score, k16 B layout) + fp16 raw (value, k16 B).
// ---------------------------------------------------------------------------
__global__ void prep_kernel(const float* __restrict__ keys, int K) {
    int row = blockIdx.x * blockDim.y + threadIdx.y;
    if (row >= K) return;
    int lane = threadIdx.x;
    float4 v = reinterpret_cast<const float4*>(keys + (size_t)row * D)[lane];
    float ss = v.x * v.x + v.y * v.y + v.z * v.z + v.w * v.w;
#pragma unroll
    for (int o = 16; o; o >>= 1) ss += __shfl_xor_sync(0xffffffffu, ss, o);
    float s = 1.0f / fmaxf(sqrtf(ss), 1e-12f);

    int t = row >> 6, kt = row & 63;
    int ng = kt >> 5, r5 = kt & 31;

    // score copy (bf16): layout [s8][j2][lane32][4]
    {
        int nt = r5 >> 3, gk = r5 & 7;
        int j = nt >> 1, npar = nt & 1;
        size_t kbase = (size_t)t * 4096 + ng * 2048 + j * 128 + 2 * npar;
        float vals[4] = {v.x, v.y, v.z, v.w};
#pragma unroll
        for (int pr = 0; pr < 2; pr++) {
            int d = 4 * lane + 2 * pr;
            int dk = d & 15;
            int sK = d >> 4, tigK = (dk >> 1) & 3, bK = (dk >> 3) & 1;
            g_kfh[kbase + sK * 256 + (4 * gk + tigK) * 4 + bK] =
                bf2(vals[2 * pr] * s, vals[2 * pr + 1] * s);
        }
    }

    // value copy (fp16): k16 B layout [kk2][jp8][lane32][4]
    {
        int kk = r5 >> 4, krel = r5 & 15;
        int hb = krel >> 3, rr = krel & 7;
        int tigV = rr >> 1, lo = rr & 1;
        size_t vbase = (size_t)t * 4096 + ng * 2048 + kk * 1024;
        __half* vh = reinterpret_cast<__half*>(g_vfh);
        float vals[4] = {v.x, v.y, v.z, v.w};
#pragma unroll
        for (int c4 = 0; c4 < 4; c4++) {
            int d = 4 * lane + c4;
            int gV = d & 7, j = d >> 3, jp = j >> 1, jo = j & 1;
            size_t u = vbase + jp * 128 + (4 * gV + tigV) * 4 + jo * 2 + hb;
            vh[u * 2 + lo] = __float2half_rn(vals[c4]);
        }
    }
}

// ---------------------------------------------------------------------------
// Query prep: bf16 (normalized * log2e), k16 A layout; slot = (row&63)>>4.
// ---------------------------------------------------------------------------
__global__ void prep_q(const float* __restrict__ queries, int N) {
    int row = blockIdx.x * blockDim.y + threadIdx.y;
    if (row >= N) return;
    int lane = threadIdx.x;
    float4 v = reinterpret_cast<const float4*>(queries + (size_t)row * D)[lane];
    float ss = v.x * v.x + v.y * v.y + v.z * v.z + v.w * v.w;
#pragma unroll
    for (int o = 16; o; o >>= 1) ss += __shfl_xor_sync(0xffffffffu, ss, o);
    float s = LOG2E / fmaxf(sqrtf(ss), 1e-12f);   // fold log2(e) -> ex2 softmax

    int cta = row >> 6, r6 = row & 63;
    int slot = r6 >> 4, rr = r6 & 15;
    int p = rr >> 3, gq = rr & 7;
    size_t qbase = (size_t)cta * 4096 + slot * 1024 + p;

    float vals[4] = {v.x, v.y, v.z, v.w};
#pragma unroll
    for (int pr = 0; pr < 2; pr++) {
        int d = 4 * lane + 2 * pr;
        int dk = d & 15;
        int sQ = d >> 4, tigQ = (dk >> 1) & 3, bQ = (dk >> 3) & 1;
        g_qfh[qbase + sQ * 128 + (4 * gq + tigQ) * 4 + 2 * bQ] =
            bf2(vals[2 * pr] * s, vals[2 * pr + 1] * s);
    }
}

// ---------------------------------------------------------------------------
// Fused flash kernel: 64 queries/CTA, 4 warps in two decoupled 2-warp groups,
// 2 CTAs/SM. GEMM1 bf16 k16; softmax via ex2; GEMM2 fp16 k16 (no shuffles).
// ---------------------------------------------------------------------------
__global__ __launch_bounds__(128, 2)
void fused_mma(float* __restrict__ out, int K) {
    extern __shared__ __align__(16) float sm[];
    const uint32_t sb = smem_u32(sm);
    const int tid  = threadIdx.x;
    const int w    = tid >> 5;
    const int lane = tid & 31;
    const int g    = lane >> 2;
    const int tig  = lane & 3;
    const int ng   = w >> 1;         // group: warps 0-1 / 2-3
    const int mg   = w & 1;          // 32-row stripe
    const int tg   = tid & 63;
    const int q0   = blockIdx.x * TQ;
    const int niter = K / TK;

    // ---- prologue: QF bf16 (1024 chunks) + group tile 0 ----
    {
        const char* qg = reinterpret_cast<const char*>(g_qfh) + (size_t)blockIdx.x * 16384;
#pragma unroll
        for (int u = 0; u < 8; u++) {
            int id = u * 128 + tid;
            cp16(sb + SM_QF + id * 16, qg + id * 16);
        }
        load_group(sb, tg, 0, ng);
        cp_commit();
        cp_wait0();
    }
    __syncthreads();

    float Oa[32][4];
#pragma unroll
    for (int i = 0; i < 32; i++)
#pragma unroll
        for (int j = 0; j < 4; j++) Oa[i][j] = 0.f;
    float dacc[4] = {0.f, 0.f, 0.f, 0.f};

    const float4* qAs = reinterpret_cast<const float4*>(sm) + (2 * mg) * 256 + lane;

    for (int it = 0; it < niter; it++) {
        if (it + 1 < niter) {          // prefetch next group chunk
            load_group(sb, tg, it + 1, ng);
            cp_commit();
        }

        const float4* kb4 = reinterpret_cast<const float4*>(sm)
                          + ((SM_GRP + ng * 32768 + (it & 1) * 16384) >> 4) + lane;
        const float4* vb4 = kb4 + 512;   // V region 8192B into the buffer

        // ---- GEMM1 (bf16 k16): S(32x32) = Qn . Kn^T ----
        float Sa[8][4];
#pragma unroll
        for (int i = 0; i < 8; i++)
#pragma unroll
            for (int j = 0; j < 4; j++) Sa[i][j] = 0.f;
#pragma unroll
        for (int s = 0; s < 8; s++) {
            float4 A0 = qAs[s * 32];
            float4 A1 = qAs[s * 32 + 256];
            float4 B0 = kb4[s * 64];
            float4 B1 = kb4[s * 64 + 32];
            MMA16BF(Sa[0], A0, B0.x, B0.y);
            MMA16BF(Sa[4], A1, B0.x, B0.y);
            MMA16BF(Sa[1], A0, B0.z, B0.w);
            MMA16BF(Sa[5], A1, B0.z, B0.w);
            MMA16BF(Sa[2], A0, B1.x, B1.y);
            MMA16BF(Sa[6], A1, B1.x, B1.y);
            MMA16BF(Sa[3], A0, B1.z, B1.w);
            MMA16BF(Sa[7], A1, B1.z, B1.w);
        }

        // ---- softmax (scores pre-scaled by log2e => bare ex2) ----
        uint32_t Ph[8][2];
#pragma unroll
        for (int mt = 0; mt < 2; mt++)
#pragma unroll
            for (int nt = 0; nt < 4; nt++) {
                const float* f = Sa[mt * 4 + nt];
                float p0 = ex2(f[0]);
                float p1 = ex2(f[1]);
                float p2 = ex2(f[2]);
                float p3 = ex2(f[3]);
                dacc[mt * 2]     += p0 + p1;
                dacc[mt * 2 + 1] += p2 + p3;
                Ph[mt * 4 + nt][0] = h2(p0, p1);   // row g
                Ph[mt * 4 + nt][1] = h2(p2, p3);   // row g+8
            }

        // ---- GEMM2 (fp16 k16): O(32x128 private) += P . V ----
#pragma unroll
        for (int kk = 0; kk < 2; kk++) {
            uint32_t A0[2], A1[2], A2[2], A3[2];
#pragma unroll
            for (int mt = 0; mt < 2; mt++) {
                A0[mt] = Ph[mt * 4 + 2 * kk][0];
                A1[mt] = Ph[mt * 4 + 2 * kk][1];
                A2[mt] = Ph[mt * 4 + 2 * kk + 1][0];
                A3[mt] = Ph[mt * 4 + 2 * kk + 1][1];
            }
            const float4* vk = vb4 + kk * 256;
#pragma unroll
            for (int jp = 0; jp < 8; jp++) {
                float4 Bf = vk[jp * 32];
                uint32_t b0 = __float_as_uint(Bf.x), b1 = __float_as_uint(Bf.y);
                uint32_t b2 = __float_as_uint(Bf.z), b3 = __float_as_uint(Bf.w);
                mma16h(Oa[2 * jp],      A0[0], A1[0], A2[0], A3[0], b0, b1);
                mma16h(Oa[16 + 2 * jp], A0[1], A1[1], A2[1], A3[1], b0, b1);
                mma16h(Oa[2 * jp + 1],      A0[0], A1[0], A2[0], A3[0], b2, b3);
                mma16h(Oa[16 + 2 * jp + 1], A0[1], A1[1], A2[1], A3[1], b2, b3);
            }
        }

        if (it + 1 < niter) {
            cp_wait0();                // next tile landed
            group_bar(ng + 1);         // group-local visibility + buffer retire
        }
    }

    __syncthreads();   // join groups; QF + group regions free for epilogue

    float* DS = sm + SM_DS / 4;

    // ---- denominators ----
#pragma unroll
    for (int r = 0; r < 4; r++) {
        dacc[r] += __shfl_xor_sync(0xffffffffu, dacc[r], 1);
        dacc[r] += __shfl_xor_sync(0xffffffffu, dacc[r], 2);
    }
    if (tig == 0) {
#pragma unroll
        for (int r = 0; r < 4; r++) {
            int row = 32 * mg + 16 * (r >> 1) + g + ((r & 1) << 3);
            DS[ng * 64 + row] = dacc[r];
        }
    }

    // ---- O pair-reduction: ng=0 publishes, ng=1 combines + writes ----
    float* Eb = sm + mg * 4224 + lane * 132;
    if (ng == 0) {
#pragma unroll
        for (int j = 0; j < 32; j++)
            *reinterpret_cast<float4*>(Eb + j * 4) =
                *reinterpret_cast<const float4*>(Oa[j]);
    }
    __syncthreads();

    if (ng == 1) {
#pragma unroll
        for (int mt = 0; mt < 2; mt++) {
            int row0 = 32 * mg + 16 * mt + g;
            float i0 = 1.0f / (DS[row0] + DS[64 + row0]);
            float i1 = 1.0f / (DS[row0 + 8] + DS[64 + row0 + 8]);
#pragma unroll
            for (int nt = 0; nt < 16; nt++) {
                int j = mt * 16 + nt;
                float4 p = *reinterpret_cast<const float4*>(Eb + j * 4);
                float2 o0 = make_float2((Oa[j][0] + p.x) * i0,
                                        (Oa[j][1] + p.y) * i0);
                float2 o1 = make_float2((Oa[j][2] + p.z) * i1,
                                        (Oa[j][3] + p.w) * i1);
                float* base = out + (size_t)(q0 + row0) * D + 8 * nt + 2 * tig;
                *reinterpret_cast<float2*>(base)         = o0;
                *reinterpret_cast<float2*>(base + 8 * D) = o1;
            }
        }
    }
}

// ---------------------------------------------------------------------------
extern "C" void kernel_launch(void* const* d_in, const int* in_sizes, int n_in,
                              void* d_out, int out_size) {
    const float* queries = (const float*)d_in[0];
    const float* keys    = (const float*)d_in[1];
    float*       out     = (float*)d_out;

    int N = in_sizes[0] / D;
    int K = in_sizes[1] / D;

    cudaFuncSetAttribute(fused_mma, cudaFuncAttributeMaxDynamicSharedMemorySize, SMEM_TOTAL);

    prep_kernel<<<(K + 7) / 8, dim3(32, 8)>>>(keys, K);
    prep_q<<<(N + 7) / 8, dim3(32, 8)>>>(queries, N);
    fused_mma<<<N / TQ, 128, SMEM_TOTAL>>>(out, K);
}